// round 13
// baseline (speedup 1.0000x reference)
#include <cuda_runtime.h>
#include <math.h>

// CNO_LReLu: antialiased bicubic upsample x2 (2048->4096), LeakyReLU(0.01),
// antialiased bicubic downsample x2 (4096->2048), per (b,c) row. B*C = 8192 rows.
//
// R12 (resubmission; broker timeout): fully-packed interior. LeakyReLU via
//   lrelu(v) = 0.505*v + 0.495*|v|
// computed packed (and.b64 + mul2 + fma2), so the f32x2 chain never unpacks
// between stage-1 and stage-2. Removes ~28 issue slots/thread vs R11
// (profile: issue 65% = top utilization). Edges keep the verified scalar path.

#define IN_SIZE  2048
#define OUT_SIZE 2048
#define NROWS    8192
#define TPB      512        // 4 outputs per thread

typedef unsigned long long u64;

__device__ __forceinline__ u64 pack2(float a, float b) {
    u64 r;
    asm("mov.b64 %0, {%1, %2};" : "=l"(r)
        : "r"(__float_as_uint(a)), "r"(__float_as_uint(b)));
    return r;
}
__device__ __forceinline__ void unpack2(u64 v, float& a, float& b) {
    unsigned x, y;
    asm("mov.b64 {%0, %1}, %2;" : "=r"(x), "=r"(y) : "l"(v));
    a = __uint_as_float(x); b = __uint_as_float(y);
}
__device__ __forceinline__ u64 fma2(u64 a, u64 b, u64 c) {
    u64 d;
    asm("fma.rn.f32x2 %0, %1, %2, %3;" : "=l"(d) : "l"(a), "l"(b), "l"(c));
    return d;
}
__device__ __forceinline__ u64 mul2(u64 a, u64 b) {
    u64 d;
    asm("mul.rn.f32x2 %0, %1, %2;" : "=l"(d) : "l"(a), "l"(b));
    return d;
}
// Packed LeakyReLU(0.01): lrelu(v) = 0.505*v + 0.495*|v|  (both lanes).
__device__ __forceinline__ u64 lrelu2(u64 v) {
    const u64 K505 = pack2(0.505f, 0.505f);
    const u64 K495 = pack2(0.495f, 0.495f);
    u64 av = v & 0x7FFFFFFF7FFFFFFFULL;       // packed |v| (2x LOP3)
    return fma2(K495, av, mul2(K505, v));
}

// Interior upsample weight vectors (exact Keys-cubic values, sum = 1):
//   odd  mid-index o: taps x[(o-1)/2-1 .. +2],  W_O
//   even mid-index o: taps x[o/2-2    .. +1],  W_E
#define WO4(a,b,c,d) fmaf(-0.0703125f,(a), fmaf(0.8671875f,(b), fmaf(0.2265625f,(c), -0.0234375f*(d))))
#define WE4(a,b,c,d) fmaf(-0.0234375f,(a), fmaf(0.2265625f,(b), fmaf(0.8671875f,(c), -0.0703125f*(d))))

__device__ __forceinline__ float lrelu(float v) {
    return fmaxf(v, 0.01f * v);   // == LeakyReLU(0.01), scalar (edge paths)
}

// Scalar stage-2 (edge threads): out = W2 . z[0..7]  (9th tap weight is 0)
__device__ __forceinline__ float stage2(const float* __restrict__ z) {
    float a =  fmaf(-0.01171875f, z[0], -0.03515625f * z[1]);
    a = fmaf( 0.11328125f, z[2], a);
    a = fmaf( 0.43359375f, z[3], a);
    a = fmaf( 0.43359375f, z[4], a);
    a = fmaf( 0.11328125f, z[5], a);
    a = fmaf(-0.03515625f, z[6], a);
    a = fmaf(-0.01171875f, z[7], a);
    return a;
}

__global__ void __launch_bounds__(TPB, 4)
cno_lrelu_kernel(const float* __restrict__ x, float* __restrict__ out) {
    const int row = blockIdx.x;
    const float* __restrict__ xr = x + (size_t)row * IN_SIZE;
    float* __restrict__ orow = out + (size_t)row * OUT_SIZE;

    const int t = threadIdx.x;

    // 12-float window; for interior threads base = 4t-4 covers x[4t-3 .. 4t+6].
    const int base = (t == 0) ? 0 : ((t == TPB - 1) ? (IN_SIZE - 12) : 4 * (t - 1));

    // Direct global loads: 3 overlapping LDG.128 (16B-aligned; each 16B chunk
    // is shared by 3 adjacent threads -> high L1 hit rate).
    float xv[12];
    #pragma unroll
    for (int q = 0; q < 3; ++q)
        *reinterpret_cast<float4*>(&xv[4 * q]) =
            *reinterpret_cast<const float4*>(&xr[base + 4 * q]);

    float4 o4;

    if (t == 0) {
        // ---- Left edge: outputs 0..3 need mid y[0..10]; y[0..2] are special ----
        float z[11];
        z[0] = fmaf(0.8671875f, xv[0], -0.0703125f * xv[1]) * (1.0f / 0.796875f);
        z[1] = fmaf(0.8671875f, xv[0], fmaf(0.2265625f, xv[1], -0.0234375f * xv[2])) * (1.0f / 1.0703125f);
        z[2] = fmaf(0.2265625f, xv[0], fmaf(0.8671875f, xv[1], -0.0703125f * xv[2])) * (1.0f / 1.0234375f);
        #pragma unroll
        for (int m = 3; m <= 10; ++m) {
            const int s = (m - 3) >> 1;
            z[m] = (m & 1) ? WO4(xv[s], xv[s+1], xv[s+2], xv[s+3])
                           : WE4(xv[s], xv[s+1], xv[s+2], xv[s+3]);
        }
        #pragma unroll
        for (int m = 0; m <= 10; ++m) z[m] = lrelu(z[m]);

        o4.x = fmaf(0.8671875f, z[0] + z[1],
               fmaf(0.2265625f, z[2],
               fmaf(-0.0703125f, z[3], -0.0234375f * z[4]))) * (1.0f / 1.8671875f);
        o4.y = (fmaf(-0.0703125f, z[0],
                fmaf( 0.2265625f, z[1],
                fmaf( 0.8671875f, z[2] + z[3],
                fmaf( 0.2265625f, z[4],
                fmaf(-0.0703125f, z[5], -0.0234375f * z[6])))))) * (1.0f / 2.0234375f);
        o4.z = stage2(z + 1);
        o4.w = stage2(z + 3);
    } else if (t == TPB - 1) {
        // ---- Right edge: outputs 2044..2047 need mid y[4085..4095] ----
        // base = 2036: xv[i] = x[2036+i]. z[j] = y[4085+j].
        float z[11];
        #pragma unroll
        for (int j = 0; j <= 7; ++j) {
            const int s = (j >> 1) + 5;
            z[j] = (j & 1) ? WE4(xv[s], xv[s+1], xv[s+2], xv[s+3])
                           : WO4(xv[s], xv[s+1], xv[s+2], xv[s+3]);
        }
        z[8]  = fmaf(-0.0703125f, xv[9], fmaf(0.8671875f, xv[10], 0.2265625f * xv[11])) * (1.0f / 1.0234375f);
        z[9]  = fmaf(-0.0234375f, xv[9], fmaf(0.2265625f, xv[10], 0.8671875f * xv[11])) * (1.0f / 1.0703125f);
        z[10] = fmaf(-0.0703125f, xv[10], 0.8671875f * xv[11]) * (1.0f / 0.796875f);
        #pragma unroll
        for (int m = 0; m <= 10; ++m) z[m] = lrelu(z[m]);

        o4.x = stage2(z + 0);   // out 2044
        o4.y = stage2(z + 2);   // out 2045
        o4.z = (fmaf(-0.0703125f, z[10],
                fmaf( 0.2265625f, z[9],
                fmaf( 0.8671875f, z[8] + z[7],
                fmaf( 0.2265625f, z[6],
                fmaf(-0.0703125f, z[5], -0.0234375f * z[4])))))) * (1.0f / 2.0234375f);
        o4.w = fmaf(0.8671875f, z[10] + z[9],
               fmaf(0.2265625f, z[8],
               fmaf(-0.0703125f, z[7], -0.0234375f * z[6]))) * (1.0f / 1.8671875f);
    } else {
        // ---- Interior, fully packed f32x2 ----
        // Pair k (k=0..6): (y[2k], y[2k+1]) both read taps xv[k+1..k+4];
        // lane lo = odd-mid weights W_O, lane hi = even-mid weights W_E.
        const u64 WP0 = pack2(-0.0703125f, -0.0234375f);
        const u64 WP1 = pack2( 0.8671875f,  0.2265625f);
        const u64 WP2 = pack2( 0.2265625f,  0.8671875f);
        const u64 WP3 = pack2(-0.0234375f, -0.0703125f);
        // Stage-2 packed weight pairs: (W2[0],W2[1]) .. (W2[6],W2[7])
        const u64 VP0 = pack2(-0.01171875f, -0.03515625f);
        const u64 VP1 = pack2( 0.11328125f,  0.43359375f);
        const u64 VP2 = pack2( 0.43359375f,  0.11328125f);
        const u64 VP3 = pack2(-0.03515625f, -0.01171875f);

        // Broadcast packs of xv[1..10] (xv[0], xv[11] are alignment padding).
        u64 xx[10];
        #pragma unroll
        for (int i = 0; i < 10; ++i) xx[i] = pack2(xv[i + 1], xv[i + 1]);

        // Rolling accumulation: Z[k] contributes to out[i] for i = k-3..k.
        u64 acc[4];
        #pragma unroll
        for (int k = 0; k < 7; ++k) {
            u64 y2 = mul2(WP0, xx[k]);
            y2 = fma2(WP1, xx[k + 1], y2);
            y2 = fma2(WP2, xx[k + 2], y2);
            y2 = fma2(WP3, xx[k + 3], y2);

            const u64 zz = lrelu2(y2);        // packed LeakyReLU, no unpack

            if (k <= 3)            acc[k]     = mul2(VP0, zz);
            if (k >= 1 && k <= 4)  acc[k - 1] = fma2(VP1, zz, acc[k - 1]);
            if (k >= 2 && k <= 5)  acc[k - 2] = fma2(VP2, zz, acc[k - 2]);
            if (k >= 3)            acc[k - 3] = fma2(VP3, zz, acc[k - 3]);
        }

        float a0, a1;
        unpack2(acc[0], a0, a1); o4.x = a0 + a1;
        unpack2(acc[1], a0, a1); o4.y = a0 + a1;
        unpack2(acc[2], a0, a1); o4.z = a0 + a1;
        unpack2(acc[3], a0, a1); o4.w = a0 + a1;
    }

    reinterpret_cast<float4*>(orow)[t] = o4;   // coalesced STG.128
}

extern "C" void kernel_launch(void* const* d_in, const int* in_sizes, int n_in,
                              void* d_out, int out_size) {
    const float* x = (const float*)d_in[0];
    float* out = (float*)d_out;
    cno_lrelu_kernel<<<NROWS, TPB>>>(x, out);
}